// round 11
// baseline (speedup 1.0000x reference)
#include <cuda_runtime.h>
#include <math.h>

// ----------------------------------------------------------------------------
// GridGRU  (D = H = 1024, N = 32, T = 512)
//
// R11:
//  * scan: two-level flag grid barrier (no same-address atomic serialization),
//          4-chunk staged cp.async tile pipeline (latency hidden under mma)
//  * GEMMs: operands pre-converted to tf32 bits once; 3-stage cp.async
//           pipelined mainloop, no in-loop cvt, 1 sync per K-tile
// ----------------------------------------------------------------------------

#define D_    1024
#define H_    1024
#define NB    32
#define TT    512
#define MROWS (NB * TT)     // 16384
#define WLD   6144          // weight row stride (2048 x 6144)
#define G3    3072
#define NBLK_SCAN 128

// Scratch (device globals: allocation-free per harness rules)
__device__ float g_gates[(size_t)MROWS * G3];   // gates, then reused as gd
__device__ float g_ht[(size_t)MROWS * H_];      // ht sequence, fp32 exact
__device__ float g_ht32[(size_t)MROWS * H_];    // ht sequence, rna(tf32)
__device__ float g_st32[NB * H_];               // state, rna(tf32)
__device__ float g_u [NB * H_];                 // per-step u gate (fp32)
__device__ float g_rh[NB * H_];                 // per-step r * h_prev (rna tf32)
__device__ float g_ud[(size_t)MROWS * D_];      // decoder update gate
__device__ float g_rx[(size_t)MROWS * D_];      // rd * x (rna tf32)
__device__ float g_w32[(size_t)2048 * WLD];     // weight, rna(tf32)
__device__ float g_x32[(size_t)MROWS * D_];     // x, rna(tf32)

// ------------------------- two-level grid barrier ---------------------------
__device__ unsigned g_arrive[NBLK_SCAN];
__device__ unsigned g_release2;

__device__ __forceinline__ unsigned ld_acq(const unsigned* p)
{
    unsigned v;
    asm volatile("ld.acquire.gpu.u32 %0, [%1];" : "=r"(v) : "l"(p));
    return v;
}
__device__ __forceinline__ void st_rel(unsigned* p, unsigned v)
{
    asm volatile("st.release.gpu.u32 [%0], %1;" :: "l"(p), "r"(v));
}

__device__ __forceinline__ void grid_barrier2(int b, int tid, unsigned gen)
{
    __syncthreads();
    if (tid == 0) st_rel(&g_arrive[b], gen);
    if (b == 0) {
        if (tid < 32) {
#pragma unroll
            for (int j = 0; j < 4; ++j) {
                while (ld_acq(&g_arrive[tid + (j << 5)]) != gen) __nanosleep(32);
            }
        }
        __syncthreads();
        if (tid == 0) st_rel(&g_release2, gen);
    }
    if (tid == 0) {
        while (ld_acq(&g_release2) != gen) __nanosleep(32);
    }
    __syncthreads();
}

// ------------------------- small asm helpers --------------------------------
__device__ __forceinline__ unsigned smem_u32(const void* p)
{
    return (unsigned)__cvta_generic_to_shared(p);
}
__device__ __forceinline__ void cp16(unsigned dst, const float* src)
{
    asm volatile("cp.async.cg.shared.global [%0], [%1], 16;" :: "r"(dst), "l"(src));
}
__device__ __forceinline__ void cp_commit()
{
    asm volatile("cp.async.commit_group;");
}
template <int N>
__device__ __forceinline__ void cp_waitN()
{
    asm volatile("cp.async.wait_group %0;" :: "n"(N));
}
__device__ __forceinline__ unsigned f2tf(float f)
{
    unsigned u;
    asm("cvt.rna.tf32.f32 %0, %1;" : "=r"(u) : "f"(f));
    return u;
}
__device__ __forceinline__ void mma_tf32(float c[4], const unsigned a[4],
                                         unsigned b0, unsigned b1)
{
    asm volatile(
        "mma.sync.aligned.m16n8k8.row.col.f32.tf32.tf32.f32 "
        "{%0,%1,%2,%3}, {%4,%5,%6,%7}, {%8,%9}, {%0,%1,%2,%3};\n"
        : "+f"(c[0]), "+f"(c[1]), "+f"(c[2]), "+f"(c[3])
        : "r"(a[0]), "r"(a[1]), "r"(a[2]), "r"(a[3]), "r"(b0), "r"(b1));
}

// ----------------------------------------------------------------------------
// Scan smem layout (floats):
//   TILE  8 warps x [32][132]  @ 0      (33792)
//   PACC  [8][16][33]          @ 33792  (4224)
//   GSM   [32][20]             @ 38016  A gates
//   HPE   [32][20]             @ 38656  A h_prev (r cols, fp32)
//   GSB   [32][12]             @ 39296  B gates
//   HPB   [32][12]             @ 39680  B h_prev (fp32)
//   UBB   [32][12]             @ 40064  B u
// total 40448 floats = 161792 B
// ----------------------------------------------------------------------------
#define TLS      132
#define TILE_F   (32 * TLS)
#define OFF_PACC 33792
#define OFF_GSM  38016
#define OFF_HPE  38656
#define OFF_GSB  39296
#define OFF_HPB  39680
#define OFF_UBB  40064
#define SMEM_FLOATS 40448

extern __shared__ float smem[];

// load one 32n x 32k chunk of a [n][k] operand into this warp's tile
__device__ __forceinline__ void load_chunk(unsigned tlu, const float* src_base,
                                           size_t nstr, int ch, int lane)
{
    const int koff = ((lane & 7) << 2) + (ch << 5);
    const int tn   = lane >> 3;
    const float* s = src_base + koff;
    const unsigned d = tlu + (unsigned)(koff << 2);
#pragma unroll
    for (int j = 0; j < 8; ++j) {
        int n = (j << 2) + tn;
        cp16(d + (unsigned)((n * TLS) << 2), s + (size_t)n * nstr);
    }
}

__global__ void __launch_bounds__(256, 1)
scan_kernel(const float* __restrict__ weight, const float* __restrict__ state)
{
    float* PACC = smem + OFF_PACC;
    float* GSM  = smem + OFF_GSM;
    float* HPE  = smem + OFF_HPE;
    float* GSB  = smem + OFF_GSB;
    float* HPB  = smem + OFF_HPB;
    float* UBB  = smem + OFF_UBB;

    const int tid  = threadIdx.x;
    const int b    = blockIdx.x;
    const int lane = tid & 31;
    const int w    = tid >> 5;
    const int gid  = lane >> 2;
    const int tg   = lane & 3;
    const int jbA  = b << 4;
    const int jbB  = b << 3;
    const int k0   = w << 7;

    float* tl = smem + w * TILE_F;
    const unsigned tlu = smem_u32(tl);
    const int f00 = gid * TLS + tg;
    const int f01 = (gid + 8) * TLS + tg;
    const int m1o = 16 * TLS;

    unsigned bar_gen = ld_acq(&g_release2);   // same for all CTAs

    // ---- preload weight fragments (rna tf32), resident all 512 steps ----
    unsigned bA0[2][16], bA1[2][16], bB0[16], bB1[16];
#pragma unroll
    for (int s = 0; s < 16; ++s) {
        const float* wr = weight + (size_t)(D_ + k0 + 8 * s + tg) * WLD;
#pragma unroll
        for (int nt = 0; nt < 2; ++nt) {
            bA0[nt][s] = f2tf(wr[jbA + nt * 8 + gid]);
            bA1[nt][s] = f2tf(wr[(size_t)4 * WLD + jbA + nt * 8 + gid]);
        }
        bB0[s] = f2tf(wr[2 * H_ + jbB + gid]);
        bB1[s] = f2tf(wr[(size_t)4 * WLD + 2 * H_ + jbB + gid]);
    }

    // prefetch gates(t=0) for phase A   [group G]
    if (tid < 128) {
        int n = tid >> 2, coff = (tid & 3) << 2;
        cp16(smem_u32(&GSM[n * 20 + coff]),
             g_gates + (size_t)n * TT * G3 + jbA + coff);
    }
    cp_commit();

    for (int t = 0; t < TT; ++t) {
        const float* hp;  size_t hstr;
        const float* hp32; size_t h32str;
        if (t == 0) { hp = state;  hstr = (size_t)H_;
                      hp32 = g_st32; h32str = (size_t)H_; }
        else        { hp = g_ht + (size_t)(t - 1) * H_; hstr = (size_t)TT * H_;
                      hp32 = g_ht32 + (size_t)(t - 1) * H_; h32str = (size_t)TT * H_; }

        // =========================== Phase A ===========================
        // groups: [G][C0=HPE+chunk0][C1][C2][C3]
        if (tid >= 128 && b >= 64) {
            int tt2 = tid - 128;
            int n = tt2 >> 2, coff = (tt2 & 3) << 2;
            cp16(smem_u32(&HPE[n * 20 + coff]),
                 hp + (size_t)n * hstr + (jbA - H_) + coff);
        }
        load_chunk(tlu, hp32 + k0, h32str, 0, lane); cp_commit();
        load_chunk(tlu, hp32 + k0, h32str, 1, lane); cp_commit();
        load_chunk(tlu, hp32 + k0, h32str, 2, lane); cp_commit();
        load_chunk(tlu, hp32 + k0, h32str, 3, lane); cp_commit();

        float cA[2][2][4];
#pragma unroll
        for (int mt = 0; mt < 2; ++mt)
#pragma unroll
            for (int nt = 0; nt < 2; ++nt)
#pragma unroll
                for (int e = 0; e < 4; ++e) cA[mt][nt][e] = 0.f;

#pragma unroll
        for (int ch = 0; ch < 4; ++ch) {
            if      (ch == 0) cp_waitN<3>();
            else if (ch == 1) cp_waitN<2>();
            else if (ch == 2) cp_waitN<1>();
            else              cp_waitN<0>();
            __syncwarp();
#pragma unroll
            for (int s = 0; s < 4; ++s) {
                const int o = 8 * (ch * 4 + s);
                unsigned am0[4], am1[4];
                am0[0] = __float_as_uint(tl[f00 + o]);
                am0[1] = __float_as_uint(tl[f01 + o]);
                am0[2] = __float_as_uint(tl[f00 + o + 4]);
                am0[3] = __float_as_uint(tl[f01 + o + 4]);
                am1[0] = __float_as_uint(tl[f00 + m1o + o]);
                am1[1] = __float_as_uint(tl[f01 + m1o + o]);
                am1[2] = __float_as_uint(tl[f00 + m1o + o + 4]);
                am1[3] = __float_as_uint(tl[f01 + m1o + o + 4]);
                mma_tf32(cA[0][0], am0, bA0[0][ch * 4 + s], bA1[0][ch * 4 + s]);
                mma_tf32(cA[0][1], am0, bA0[1][ch * 4 + s], bA1[1][ch * 4 + s]);
                mma_tf32(cA[1][0], am1, bA0[0][ch * 4 + s], bA1[0][ch * 4 + s]);
                mma_tf32(cA[1][1], am1, bA0[1][ch * 4 + s], bA1[1][ch * 4 + s]);
            }
        }

#pragma unroll
        for (int mt = 0; mt < 2; ++mt)
#pragma unroll
            for (int nt = 0; nt < 2; ++nt)
#pragma unroll
                for (int e = 0; e < 4; ++e) {
                    int row = mt * 16 + gid + ((e >> 1) << 3);
                    int col = nt * 8 + 2 * tg + (e & 1);
                    PACC[w * 528 + col * 33 + row] = cA[mt][nt][e];
                }
        __syncthreads();

        {   // combine + sigmoid + store u / rh (rh stored rna-rounded)
            float* dst = (b < 64) ? g_u : g_rh;
            const int jb0 = (b < 64) ? jbA : (jbA - H_);
#pragma unroll
            for (int s2 = 0; s2 < 2; ++s2) {
                int idx = tid + (s2 << 8);
                int c = idx & 15, n = idx >> 4;
                float z = GSM[n * 20 + c];
#pragma unroll
                for (int g = 0; g < 8; ++g) z += PACC[g * 528 + c * 33 + n];
                float s = 1.f / (1.f + expf(-z));
                float o;
                if (b < 64) o = s;
                else        o = __uint_as_float(f2tf(s * HPE[n * 20 + c]));
                dst[n * H_ + jb0 + c] = o;
            }
        }
        // pre-barrier staging for phase B    [group Y]
        if (tid < 64) {
            int n = tid >> 1, coff = (tid & 1) << 2;
            cp16(smem_u32(&GSB[n * 12 + coff]),
                 g_gates + (size_t)n * TT * G3 + (size_t)t * G3 + 2 * H_ + jbB + coff);
        } else if (tid < 128) {
            int tt2 = tid - 64;
            int n = tt2 >> 1, coff = (tt2 & 1) << 2;
            cp16(smem_u32(&HPB[n * 12 + coff]),
                 hp + (size_t)n * hstr + jbB + coff);
        }
        cp_commit();
        ++bar_gen;
        grid_barrier2(b, tid, bar_gen);

        // =========================== Phase B ===========================
        // groups: [Y][C0=UBB+chunk0][C1][C2][C3]
        if (tid < 64) {
            int n = tid >> 1, coff = (tid & 1) << 2;
            cp16(smem_u32(&UBB[n * 12 + coff]), g_u + n * H_ + jbB + coff);
        }
        load_chunk(tlu, g_rh + k0, (size_t)H_, 0, lane); cp_commit();
        load_chunk(tlu, g_rh + k0, (size_t)H_, 1, lane); cp_commit();
        load_chunk(tlu, g_rh + k0, (size_t)H_, 2, lane); cp_commit();
        load_chunk(tlu, g_rh + k0, (size_t)H_, 3, lane); cp_commit();

        float cB[2][4];
#pragma unroll
        for (int mt = 0; mt < 2; ++mt)
#pragma unroll
            for (int e = 0; e < 4; ++e) cB[mt][e] = 0.f;

#pragma unroll
        for (int ch = 0; ch < 4; ++ch) {
            if      (ch == 0) cp_waitN<3>();
            else if (ch == 1) cp_waitN<2>();
            else if (ch == 2) cp_waitN<1>();
            else              cp_waitN<0>();
            __syncwarp();
#pragma unroll
            for (int s = 0; s < 4; ++s) {
                const int o = 8 * (ch * 4 + s);
                unsigned am0[4], am1[4];
                am0[0] = __float_as_uint(tl[f00 + o]);
                am0[1] = __float_as_uint(tl[f01 + o]);
                am0[2] = __float_as_uint(tl[f00 + o + 4]);
                am0[3] = __float_as_uint(tl[f01 + o + 4]);
                am1[0] = __float_as_uint(tl[f00 + m1o + o]);
                am1[1] = __float_as_uint(tl[f01 + m1o + o]);
                am1[2] = __float_as_uint(tl[f00 + m1o + o + 4]);
                am1[3] = __float_as_uint(tl[f01 + m1o + o + 4]);
                mma_tf32(cB[0], am0, bB0[ch * 4 + s], bB1[ch * 4 + s]);
                mma_tf32(cB[1], am1, bB0[ch * 4 + s], bB1[ch * 4 + s]);
            }
        }

#pragma unroll
        for (int mt = 0; mt < 2; ++mt)
#pragma unroll
            for (int e = 0; e < 4; ++e) {
                int row = mt * 16 + gid + ((e >> 1) << 3);
                int col = 2 * tg + (e & 1);
                PACC[w * 528 + col * 33 + row] = cB[mt][e];
            }
        __syncthreads();

        {   // combine + tanh + h update; store fp32 h and rna copy
            int c = tid & 7, n = tid >> 3;
            float z = GSB[n * 12 + c];
#pragma unroll
            for (int g = 0; g < 8; ++g) z += PACC[g * 528 + c * 33 + n];
            float hc = tanhf(z);
            float hv = HPB[n * 12 + c];
            float u  = UBB[n * 12 + c];
            float h  = fmaf(u, hc - hv, hv);
            size_t off = (size_t)n * TT * H_ + (size_t)t * H_ + jbB + c;
            g_ht[off]   = h;
            g_ht32[off] = __uint_as_float(f2tf(h));
        }
        // prefetch gates(t+1)   [group G]
        if (t + 1 < TT && tid < 128) {
            int n = tid >> 2, coff = (tid & 3) << 2;
            cp16(smem_u32(&GSM[n * 20 + coff]),
                 g_gates + (size_t)n * TT * G3 + (size_t)(t + 1) * G3 + jbA + coff);
        }
        cp_commit();
        ++bar_gen;
        grid_barrier2(b, tid, bar_gen);
    }
}

// ----------------------------------------------------------------------------
// One-shot rna(tf32) conversion of weight, x, state
// ----------------------------------------------------------------------------
__global__ void __launch_bounds__(256)
conv_kernel(const float* __restrict__ wsrc, const float* __restrict__ xsrc,
            const float* __restrict__ stsrc)
{
    const int stride = gridDim.x * 256;
    int tid = blockIdx.x * 256 + threadIdx.x;
    const size_t WQ = (size_t)2048 * WLD / 4;
    const size_t XQ = (size_t)MROWS * D_ / 4;
    const size_t SQ = (size_t)NB * H_ / 4;
    for (size_t i = tid; i < WQ; i += stride) {
        float4 v = ((const float4*)wsrc)[i];
        ((uint4*)g_w32)[i] = make_uint4(f2tf(v.x), f2tf(v.y), f2tf(v.z), f2tf(v.w));
    }
    for (size_t i = tid; i < XQ; i += stride) {
        float4 v = ((const float4*)xsrc)[i];
        ((uint4*)g_x32)[i] = make_uint4(f2tf(v.x), f2tf(v.y), f2tf(v.z), f2tf(v.w));
    }
    for (size_t i = tid; i < SQ; i += stride) {
        float4 v = ((const float4*)stsrc)[i];
        ((uint4*)g_st32)[i] = make_uint4(f2tf(v.x), f2tf(v.y), f2tf(v.z), f2tf(v.w));
    }
}

// ----------------------------------------------------------------------------
// TF32 GEMM, operands pre-converted: 3-stage cp.async pipeline.
// 128x128x16 CTA tile, 8 warps (4m x 2n), warp tile 32x64, m16n8k8.
// MODE 0: C = acc + bias[col]
// MODE 1: s = sigmoid(gd + acc); col<D -> ud, else rx = rna(s * x)
// MODE 2: hcd = tanh(gd + acc); C = x + ud*(hcd - x)
// ----------------------------------------------------------------------------
#define ALD 20
#define BLD 136
#define STAGE_F (128 * ALD + 16 * BLD)   // 4736 floats
#define GEMM_SMEM (3 * STAGE_F * 4)      // 56832 B

template <int MODE>
__global__ void __launch_bounds__(256, 2)
tgemm2(const float* __restrict__ A, int lda,
       const float* __restrict__ B, int ldb,
       const float* __restrict__ bias,
       float* __restrict__ C, int ldc,
       const float* __restrict__ gdp,
       const float* __restrict__ xp,
       float* __restrict__ udp,
       float* __restrict__ rxp)
{
    extern __shared__ float sm[];

    const int tid  = threadIdx.x;
    const int lane = tid & 31;
    const int warp = tid >> 5;
    const int gid  = lane >> 2;
    const int tg   = lane & 3;
    const int wm   = warp & 3;
    const int wn   = warp >> 2;

    const int rowBase = blockIdx.y << 7;
    const int colBase = blockIdx.x << 7;

    const int arow = tid >> 1;
    const int ak   = (tid & 1) << 3;
    const int bk   = tid >> 4;
    const int bn   = (tid & 15) << 3;

    const float* Ag = A + (size_t)(rowBase + arow) * lda + ak;
    const float* Bg = B + (size_t)bk * ldb + colBase + bn;

    float c[2][8][4];
#pragma unroll
    for (int mt = 0; mt < 2; ++mt)
#pragma unroll
        for (int nt = 0; nt < 8; ++nt)
#pragma unroll
            for (int e = 0; e < 4; ++e) c[mt][nt][e] = 0.f;

    const int NIT = 64;   // K = 1024 / 16

    // issue stage kt into buffer buf
    auto issue = [&](int kt, int buf) {
        float* As = sm + buf * STAGE_F;
        float* Bs = As + 128 * ALD;
        const float* ap = Ag + kt * 16;
        const float* bp = Bg + (size_t)kt * 16 * ldb;
        cp16(smem_u32(&As[arow * ALD + ak]),     ap);
        cp16(smem_u32(&As[arow * ALD + ak + 4]), ap + 4);
        cp16(smem_u32(&Bs[bk * BLD + bn]),       bp);
        cp16(smem_u32(&Bs[bk * BLD + bn + 4]),   bp + 4);
    };

    issue(0, 0); cp_commit();
    issue(1, 1); cp_commit();

#pragma unroll 1
    for (int kt = 0; kt < NIT; ++kt) {
        cp_waitN<1>();
        __syncthreads();
        if (kt + 2 < NIT) issue(kt + 2, (kt + 2) % 3);
        cp_commit();

        const float* As = sm + (kt % 3) * STAGE_F;
        const float* Bs = As + 128 * ALD;
#pragma unroll
        for (int ks = 0; ks < 2; ++ks) {
            unsigned a[2][4];
#pragma unroll
            for (int mt = 0; mt < 2; ++mt) {
                const int r = (wm * 32 + mt * 16 + gid) * ALD + ks * 8 + tg;
                a[mt][0] = __float_as_uint(As[r]);
                a[mt][1] = __float_as_uint(As[r + 8 * ALD]);
                a[mt][2] = __float_as_uint(As[r + 4]);
                a[mt][3] = __float_as_uint(As[r + 8 * ALD + 4]);
            }
#pragma unroll
            for (int nt = 0; nt < 8; ++nt) {
                const int nidx = wn * 64 + nt * 8 + gid;
                const unsigned b0 = __float_as_uint(Bs[(ks * 8 + tg) * BLD + nidx]);
                const unsigned b1 = __float_as_uint(Bs[(ks * 8 + tg + 4) * BLD + nidx]);
                mma_tf32(c[0][nt], a[0], b0, b1);
                mma_tf32(c[1][nt], a[1], b0, b1);
            }
        }
    }

#pragma unroll
    for (int mt = 0; mt < 2; ++mt) {
#pragma unroll
        for (int nt = 0; nt < 8; ++nt) {
#pragma unroll
            for (int e = 0; e < 4; ++e) {
                const int m   = rowBase + wm * 32 + mt * 16 + gid + (e >> 1) * 8;
                const int col = colBase + wn * 64 + nt * 8 + tg * 2 + (e & 1);
                const float v = c[mt][nt][e];
                if (MODE == 0) {
                    C[(size_t)m * ldc + col] = v + bias[col];
                } else if (MODE == 1) {
                    float s = 1.f / (1.f + expf(-(gdp[(size_t)m * G3 + col] + v)));
                    if (col < D_) {
                        udp[(size_t)m * D_ + col] = s;
                    } else {
                        const int d = col - D_;
                        rxp[(size_t)m * D_ + d] =
                            __uint_as_float(f2tf(s * xp[(size_t)m * D_ + d]));
                    }
                } else {
                    float hcd = tanhf(gdp[(size_t)m * G3 + 2 * D_ + col] + v);
                    float xv  = xp[(size_t)m * D_ + col];
                    C[(size_t)m * D_ + col] =
                        fmaf(udp[(size_t)m * D_ + col], hcd - xv, xv);
                }
            }
        }
    }
}

// final_ht = ht[:, T-1, :]
__global__ void __launch_bounds__(256)
copy_final(float* __restrict__ out)
{
    int i = blockIdx.x * 256 + threadIdx.x;
    int n = i >> 10, h = i & 1023;
    out[i] = g_ht[(size_t)n * TT * H_ + (size_t)(TT - 1) * H_ + h];
}

// ----------------------------------------------------------------------------
extern "C" void kernel_launch(void* const* d_in, const int* in_sizes, int n_in,
                              void* d_out, int out_size)
{
    const float* x      = (const float*)d_in[0];
    const float* state  = (const float*)d_in[1];
    const float* weight = (const float*)d_in[2];
    const float* bias   = (const float*)d_in[3];
    float*       out    = (float*)d_out;

    float *gates, *ht32, *ud, *rx, *w32, *x32;
    cudaGetSymbolAddress((void**)&gates, g_gates);
    cudaGetSymbolAddress((void**)&ht32,  g_ht32);
    cudaGetSymbolAddress((void**)&ud,    g_ud);
    cudaGetSymbolAddress((void**)&rx,    g_rx);
    cudaGetSymbolAddress((void**)&w32,   g_w32);
    cudaGetSymbolAddress((void**)&x32,   g_x32);

    const dim3 blk(256);
    const int scan_smem = SMEM_FLOATS * 4;   // 161792 B

    cudaFuncSetAttribute(scan_kernel,
                         cudaFuncAttributeMaxDynamicSharedMemorySize, scan_smem);
    cudaFuncSetAttribute(tgemm2<0>,
                         cudaFuncAttributeMaxDynamicSharedMemorySize, GEMM_SMEM);
    cudaFuncSetAttribute(tgemm2<1>,
                         cudaFuncAttributeMaxDynamicSharedMemorySize, GEMM_SMEM);
    cudaFuncSetAttribute(tgemm2<2>,
                         cudaFuncAttributeMaxDynamicSharedMemorySize, GEMM_SMEM);

    // pre-convert weight / x / state to tf32 bits
    conv_kernel<<<1024, blk>>>(weight, x, state);

    // K1: gates = x @ Wxt + bias[:3H]
    tgemm2<0><<<dim3(G3 / 128, MROWS / 128), blk, GEMM_SMEM>>>(
        x32, 1024, w32, WLD, bias, gates, G3,
        nullptr, nullptr, nullptr, nullptr);

    // Persistent scan: 512 steps in ONE launch
    scan_kernel<<<NBLK_SCAN, blk, scan_smem>>>(weight, state);

    // K3: gd = ht @ Whd + bias[3H:]
    tgemm2<0><<<dim3(G3 / 128, MROWS / 128), blk, GEMM_SMEM>>>(
        ht32, 1024, w32 + (size_t)D_ * WLD + G3, WLD, bias + G3, gates, G3,
        nullptr, nullptr, nullptr, nullptr);

    // K4: g2 = sigmoid(gd[:, :2D] + x @ Wxd[:, :2D]) -> ud, rx
    tgemm2<1><<<dim3(2048 / 128, MROWS / 128), blk, GEMM_SMEM>>>(
        x32, 1024, w32 + G3, WLD, nullptr, nullptr, 0,
        gates, x, ud, rx);

    // K5: h = x + ud * (tanh(gd[:, 2D:] + rx @ Wxd[:, 2D:]) - x)
    tgemm2<2><<<dim3(1024 / 128, MROWS / 128), blk, GEMM_SMEM>>>(
        rx, 1024, w32 + G3 + 2 * D_, WLD, nullptr, out, D_,
        gates, x, ud, nullptr);

    // final_ht
    copy_final<<<128, blk>>>(out + (size_t)MROWS * D_);
}

// round 12
// speedup vs baseline: 1.1868x; 1.1868x over previous
#include <cuda_runtime.h>
#include <math.h>

// ----------------------------------------------------------------------------
// GridGRU  (D = H = 1024, N = 32, T = 512)
//
// R12 = R10 scan (atomic ticket barrier, monolithic cp.async tiles — the
// measured-fast variant) + R11 GEMM path (pre-converted tf32 operands,
// 3-stage cp.async pipelined tgemm2).
// ----------------------------------------------------------------------------

#define D_    1024
#define H_    1024
#define NB    32
#define TT    512
#define MROWS (NB * TT)     // 16384
#define WLD   6144          // weight row stride (2048 x 6144)
#define G3    3072
#define NBLK_SCAN 128

// Scratch (device globals: allocation-free per harness rules)
__device__ float g_gates[(size_t)MROWS * G3];   // gates, then reused as gd
__device__ float g_ht[(size_t)MROWS * H_];      // ht sequence, fp32 exact
__device__ float g_ht32[(size_t)MROWS * H_];    // ht sequence, rna(tf32)
__device__ float g_st32[NB * H_];               // state, rna(tf32)
__device__ float g_u [NB * H_];                 // per-step u gate (fp32)
__device__ float g_rh[NB * H_];                 // per-step r * h_prev (rna tf32)
__device__ float g_ud[(size_t)MROWS * D_];      // decoder update gate
__device__ float g_rx[(size_t)MROWS * D_];      // rd * x (rna tf32)
__device__ float g_w32[(size_t)2048 * WLD];     // weight, rna(tf32)
__device__ float g_x32[(size_t)MROWS * D_];     // x, rna(tf32)

// ------------------------- software grid barrier (R10) ----------------------
__device__ unsigned int g_bar_count = 0;
__device__ unsigned int g_bar_gen   = 0;

__device__ __forceinline__ void grid_barrier()
{
    __syncthreads();
    __threadfence();
    if (threadIdx.x == 0) {
        unsigned int gen = *(volatile unsigned int*)&g_bar_gen;
        unsigned int tk  = atomicAdd(&g_bar_count, 1u);
        if (tk == NBLK_SCAN - 1) {
            g_bar_count = 0;
            __threadfence();
            *(volatile unsigned int*)&g_bar_gen = gen + 1u;
        } else {
            while (*(volatile unsigned int*)&g_bar_gen == gen) { __nanosleep(32); }
        }
        __threadfence();
    }
    __syncthreads();
}

// ------------------------- small asm helpers --------------------------------
__device__ __forceinline__ unsigned smem_u32(const void* p)
{
    return (unsigned)__cvta_generic_to_shared(p);
}
__device__ __forceinline__ void cp16(unsigned dst, const float* src)
{
    asm volatile("cp.async.cg.shared.global [%0], [%1], 16;" :: "r"(dst), "l"(src));
}
__device__ __forceinline__ void cp_commit()
{
    asm volatile("cp.async.commit_group;");
}
__device__ __forceinline__ void cp_wait0()
{
    asm volatile("cp.async.wait_group 0;");
}
template <int N>
__device__ __forceinline__ void cp_waitN()
{
    asm volatile("cp.async.wait_group %0;" :: "n"(N));
}
__device__ __forceinline__ unsigned f2tf(float f)
{
    unsigned u;
    asm("cvt.rna.tf32.f32 %0, %1;" : "=r"(u) : "f"(f));
    return u;
}
__device__ __forceinline__ void mma_tf32(float c[4], const unsigned a[4],
                                         unsigned b0, unsigned b1)
{
    asm volatile(
        "mma.sync.aligned.m16n8k8.row.col.f32.tf32.tf32.f32 "
        "{%0,%1,%2,%3}, {%4,%5,%6,%7}, {%8,%9}, {%0,%1,%2,%3};\n"
        : "+f"(c[0]), "+f"(c[1]), "+f"(c[2]), "+f"(c[3])
        : "r"(a[0]), "r"(a[1]), "r"(a[2]), "r"(a[3]), "r"(b0), "r"(b1));
}

// ----------------------------------------------------------------------------
// Scan smem layout (floats):
//   TILE  8 warps x [32][132]  @ 0      (33792)
//   PACC  [8][16][33]          @ 33792  (4224)
//   GSM   [32][20]             @ 38016  A gates
//   HPE   [32][20]             @ 38656  A h_prev (r cols, fp32)
//   GSB   [32][12]             @ 39296  B gates
//   HPB   [32][12]             @ 39680  B h_prev (fp32)
//   UBB   [32][12]             @ 40064  B u
// total 40448 floats = 161792 B
// ----------------------------------------------------------------------------
#define TLS      132
#define TILE_F   (32 * TLS)
#define OFF_PACC 33792
#define OFF_GSM  38016
#define OFF_HPE  38656
#define OFF_GSB  39296
#define OFF_HPB  39680
#define OFF_UBB  40064
#define SMEM_FLOATS 40448

extern __shared__ float smem[];

__global__ void __launch_bounds__(256, 1)
scan_kernel(const float* __restrict__ weight, const float* __restrict__ state)
{
    float* PACC = smem + OFF_PACC;
    float* GSM  = smem + OFF_GSM;
    float* HPE  = smem + OFF_HPE;
    float* GSB  = smem + OFF_GSB;
    float* HPB  = smem + OFF_HPB;
    float* UBB  = smem + OFF_UBB;

    const int tid  = threadIdx.x;
    const int b    = blockIdx.x;
    const int lane = tid & 31;
    const int w    = tid >> 5;
    const int gid  = lane >> 2;
    const int tg   = lane & 3;
    const int jbA  = b << 4;
    const int jbB  = b << 3;
    const int k0   = w << 7;            // warp K-slice base

    float* tl = smem + w * TILE_F;
    const unsigned tlu = smem_u32(tl);

    // fragment smem offsets (floats): A rows = batch n
    const int f00 = gid * TLS + tg;            // (gid,   tg)
    const int f01 = (gid + 8) * TLS + tg;      // (gid+8, tg)
    const int m1o = 16 * TLS;

    // ---- preload weight fragments (rna tf32), resident all 512 steps ----
    unsigned bA0[2][16], bA1[2][16], bB0[16], bB1[16];
#pragma unroll
    for (int s = 0; s < 16; ++s) {
        const float* wr = weight + (size_t)(D_ + k0 + 8 * s + tg) * WLD;
#pragma unroll
        for (int nt = 0; nt < 2; ++nt) {
            bA0[nt][s] = f2tf(wr[jbA + nt * 8 + gid]);
            bA1[nt][s] = f2tf(wr[(size_t)4 * WLD + jbA + nt * 8 + gid]);
        }
        bB0[s] = f2tf(wr[2 * H_ + jbB + gid]);
        bB1[s] = f2tf(wr[(size_t)4 * WLD + 2 * H_ + jbB + gid]);
    }

    // prefetch gates(t=0) for phase A
    if (tid < 128) {
        int n = tid >> 2, coff = (tid & 3) << 2;
        cp16(smem_u32(&GSM[n * 20 + coff]),
             g_gates + (size_t)n * TT * G3 + jbA + coff);
    }
    cp_commit();

    for (int t = 0; t < TT; ++t) {
        const float* hp;  size_t hstr;     // fp32 h_prev
        const float* hp32; size_t h32str;  // rna h_prev
        if (t == 0) { hp = state;  hstr = (size_t)H_;
                      hp32 = g_st32; h32str = (size_t)H_; }
        else        { hp = g_ht + (size_t)(t - 1) * H_; hstr = (size_t)TT * H_;
                      hp32 = g_ht32 + (size_t)(t - 1) * H_; h32str = (size_t)TT * H_; }

        // =========================== Phase A ===========================
        // tile: this warp's K-slice of h32, [n][k] stride TLS
        {
            const float* src = hp32 + k0 + (lane << 2);
            const unsigned d0 = tlu + (lane << 4);
#pragma unroll 8
            for (int n = 0; n < 32; ++n)
                cp16(d0 + (unsigned)((n * TLS) << 2), src + (size_t)n * h32str);
        }
        if (tid >= 128 && b >= 64) {   // h_prev (fp32) for r-cols
            int tt2 = tid - 128;
            int n = tt2 >> 2, coff = (tt2 & 3) << 2;
            cp16(smem_u32(&HPE[n * 20 + coff]),
                 hp + (size_t)n * hstr + (jbA - H_) + coff);
        }
        cp_commit();
        cp_wait0();

        float cA[2][2][4];
#pragma unroll
        for (int mt = 0; mt < 2; ++mt)
#pragma unroll
            for (int nt = 0; nt < 2; ++nt)
#pragma unroll
                for (int e = 0; e < 4; ++e) cA[mt][nt][e] = 0.f;

#pragma unroll
        for (int s = 0; s < 16; ++s) {
            const int o = 8 * s;
            unsigned am0[4], am1[4];
            am0[0] = __float_as_uint(tl[f00 + o]);
            am0[1] = __float_as_uint(tl[f01 + o]);
            am0[2] = __float_as_uint(tl[f00 + o + 4]);
            am0[3] = __float_as_uint(tl[f01 + o + 4]);
            am1[0] = __float_as_uint(tl[f00 + m1o + o]);
            am1[1] = __float_as_uint(tl[f01 + m1o + o]);
            am1[2] = __float_as_uint(tl[f00 + m1o + o + 4]);
            am1[3] = __float_as_uint(tl[f01 + m1o + o + 4]);
            mma_tf32(cA[0][0], am0, bA0[0][s], bA1[0][s]);
            mma_tf32(cA[0][1], am0, bA0[1][s], bA1[1][s]);
            mma_tf32(cA[1][0], am1, bA0[0][s], bA1[0][s]);
            mma_tf32(cA[1][1], am1, bA0[1][s], bA1[1][s]);
        }

        // K-partials -> PACC
#pragma unroll
        for (int mt = 0; mt < 2; ++mt)
#pragma unroll
            for (int nt = 0; nt < 2; ++nt)
#pragma unroll
                for (int e = 0; e < 4; ++e) {
                    int row = mt * 16 + gid + ((e >> 1) << 3);
                    int col = nt * 8 + 2 * tg + (e & 1);
                    PACC[w * 528 + col * 33 + row] = cA[mt][nt][e];
                }
        __syncthreads();

        // combine + sigmoid + store u / rh (rh stored rna-rounded)
        {
            float* dst = (b < 64) ? g_u : g_rh;
            const int jb0 = (b < 64) ? jbA : (jbA - H_);
#pragma unroll
            for (int s2 = 0; s2 < 2; ++s2) {
                int idx = tid + (s2 << 8);
                int c = idx & 15, n = idx >> 4;
                float z = GSM[n * 20 + c];
#pragma unroll
                for (int g = 0; g < 8; ++g) z += PACC[g * 528 + c * 33 + n];
                float s = 1.f / (1.f + expf(-z));
                float o;
                if (b < 64) o = s;
                else        o = __uint_as_float(f2tf(s * HPE[n * 20 + c]));
                dst[n * H_ + jb0 + c] = o;
            }
        }
        // pre-barrier staging for phase B (gates + h_prev)
        if (tid < 64) {
            int n = tid >> 1, coff = (tid & 1) << 2;
            cp16(smem_u32(&GSB[n * 12 + coff]),
                 g_gates + (size_t)n * TT * G3 + (size_t)t * G3 + 2 * H_ + jbB + coff);
        } else if (tid < 128) {
            int tt2 = tid - 64;
            int n = tt2 >> 1, coff = (tt2 & 1) << 2;
            cp16(smem_u32(&HPB[n * 12 + coff]),
                 hp + (size_t)n * hstr + jbB + coff);
        }
        cp_commit();
        grid_barrier();

        // =========================== Phase B ===========================
        {
            const float* src = g_rh + k0 + (lane << 2);
            const unsigned d0 = tlu + (lane << 4);
#pragma unroll 8
            for (int n = 0; n < 32; ++n)
                cp16(d0 + (unsigned)((n * TLS) << 2), src + n * H_);
        }
        if (tid < 64) {
            int n = tid >> 1, coff = (tid & 1) << 2;
            cp16(smem_u32(&UBB[n * 12 + coff]), g_u + n * H_ + jbB + coff);
        }
        cp_commit();
        cp_wait0();

        float cB[2][4];
#pragma unroll
        for (int mt = 0; mt < 2; ++mt)
#pragma unroll
            for (int e = 0; e < 4; ++e) cB[mt][e] = 0.f;

#pragma unroll
        for (int s = 0; s < 16; ++s) {
            const int o = 8 * s;
            unsigned am0[4], am1[4];
            am0[0] = __float_as_uint(tl[f00 + o]);
            am0[1] = __float_as_uint(tl[f01 + o]);
            am0[2] = __float_as_uint(tl[f00 + o + 4]);
            am0[3] = __float_as_uint(tl[f01 + o + 4]);
            am1[0] = __float_as_uint(tl[f00 + m1o + o]);
            am1[1] = __float_as_uint(tl[f01 + m1o + o]);
            am1[2] = __float_as_uint(tl[f00 + m1o + o + 4]);
            am1[3] = __float_as_uint(tl[f01 + m1o + o + 4]);
            mma_tf32(cB[0], am0, bB0[s], bB1[s]);
            mma_tf32(cB[1], am1, bB0[s], bB1[s]);
        }

#pragma unroll
        for (int mt = 0; mt < 2; ++mt)
#pragma unroll
            for (int e = 0; e < 4; ++e) {
                int row = mt * 16 + gid + ((e >> 1) << 3);
                int col = 2 * tg + (e & 1);
                PACC[w * 528 + col * 33 + row] = cB[mt][e];
            }
        __syncthreads();

        // combine + tanh + h update; store fp32 h and rna copy
        {
            int c = tid & 7, n = tid >> 3;
            float z = GSB[n * 12 + c];
#pragma unroll
            for (int g = 0; g < 8; ++g) z += PACC[g * 528 + c * 33 + n];
            float hc = tanhf(z);
            float hv = HPB[n * 12 + c];
            float u  = UBB[n * 12 + c];
            float h  = fmaf(u, hc - hv, hv);
            size_t off = (size_t)n * TT * H_ + (size_t)t * H_ + jbB + c;
            g_ht[off]   = h;
            g_ht32[off] = __uint_as_float(f2tf(h));
        }
        // prefetch gates(t+1) for next phase A
        if (t + 1 < TT && tid < 128) {
            int n = tid >> 2, coff = (tid & 3) << 2;
            cp16(smem_u32(&GSM[n * 20 + coff]),
                 g_gates + (size_t)n * TT * G3 + (size_t)(t + 1) * G3 + jbA + coff);
        }
        cp_commit();
        grid_barrier();
    }
}

// ----------------------------------------------------------------------------
// One-shot rna(tf32) conversion of weight, x, state
// ----------------------------------------------------------------------------
__global__ void __launch_bounds__(256)
conv_kernel(const float* __restrict__ wsrc, const float* __restrict__ xsrc,
            const float* __restrict__ stsrc)
{
    const int stride = gridDim.x * 256;
    int tid = blockIdx.x * 256 + threadIdx.x;
    const size_t WQ = (size_t)2048 * WLD / 4;
    const size_t XQ = (size_t)MROWS * D_ / 4;
    const size_t SQ = (size_t)NB * H_ / 4;
    for (size_t i = tid; i < WQ; i += stride) {
        float4 v = ((const float4*)wsrc)[i];
        ((uint4*)g_w32)[i] = make_uint4(f2tf(v.x), f2tf(v.y), f2tf(v.z), f2tf(v.w));
    }
    for (size_t i = tid; i < XQ; i += stride) {
        float4 v = ((const float4*)xsrc)[i];
        ((uint4*)g_x32)[i] = make_uint4(f2tf(v.x), f2tf(v.y), f2tf(v.z), f2tf(v.w));
    }
    for (size_t i = tid; i < SQ; i += stride) {
        float4 v = ((const float4*)stsrc)[i];
        ((uint4*)g_st32)[i] = make_uint4(f2tf(v.x), f2tf(v.y), f2tf(v.z), f2tf(v.w));
    }
}

// ----------------------------------------------------------------------------
// TF32 GEMM, operands pre-converted: 3-stage cp.async pipeline (R11).
// 128x128x16 CTA tile, 8 warps (4m x 2n), warp tile 32x64, m16n8k8.
// MODE 0: C = acc + bias[col]
// MODE 1: s = sigmoid(gd + acc); col<D -> ud, else rx = rna(s * x)
// MODE 2: hcd = tanh(gd + acc); C = x + ud*(hcd - x)
// ----------------------------------------------------------------------------
#define ALD 20
#define BLD 136
#define STAGE_F (128 * ALD + 16 * BLD)   // 4736 floats
#define GEMM_SMEM (3 * STAGE_F * 4)      // 56832 B

template <int MODE>
__global__ void __launch_bounds__(256, 2)
tgemm2(const float* __restrict__ A, int lda,
       const float* __restrict__ B, int ldb,
       const float* __restrict__ bias,
       float* __restrict__ C, int ldc,
       const float* __restrict__ gdp,
       const float* __restrict__ xp,
       float* __restrict__ udp,
       float* __restrict__ rxp)
{
    extern __shared__ float sm[];

    const int tid  = threadIdx.x;
    const int lane = tid & 31;
    const int warp = tid >> 5;
    const int gid  = lane >> 2;
    const int tg   = lane & 3;
    const int wm   = warp & 3;
    const int wn   = warp >> 2;

    const int rowBase = blockIdx.y << 7;
    const int colBase = blockIdx.x << 7;

    const int arow = tid >> 1;
    const int ak   = (tid & 1) << 3;
    const int bk   = tid >> 4;
    const int bn   = (tid & 15) << 3;

    const float* Ag = A + (size_t)(rowBase + arow) * lda + ak;
    const float* Bg = B + (size_t)bk * ldb + colBase + bn;

    float c[2][8][4];
#pragma unroll
    for (int mt = 0; mt < 2; ++mt)
#pragma unroll
        for (int nt = 0; nt < 8; ++nt)
#pragma unroll
            for (int e = 0; e < 4; ++e) c[mt][nt][e] = 0.f;

    const int NIT = 64;   // K = 1024 / 16

    auto issue = [&](int kt, int buf) {
        float* As = sm + buf * STAGE_F;
        float* Bs = As + 128 * ALD;
        const float* ap = Ag + kt * 16;
        const float* bp = Bg + (size_t)kt * 16 * ldb;
        cp16(smem_u32(&As[arow * ALD + ak]),     ap);
        cp16(smem_u32(&As[arow * ALD + ak + 4]), ap + 4);
        cp16(smem_u32(&Bs[bk * BLD + bn]),       bp);
        cp16(smem_u32(&Bs[bk * BLD + bn + 4]),   bp + 4);
    };

    issue(0, 0); cp_commit();
    issue(1, 1); cp_commit();

#pragma unroll 1
    for (int kt = 0; kt < NIT; ++kt) {
        cp_waitN<1>();
        __syncthreads();
        if (kt + 2 < NIT) issue(kt + 2, (kt + 2) % 3);
        cp_commit();

        const float* As = sm + (kt % 3) * STAGE_F;
        const float* Bs = As + 128 * ALD;
#pragma unroll
        for (int ks = 0; ks < 2; ++ks) {
            unsigned a[2][4];
#pragma unroll
            for (int mt = 0; mt < 2; ++mt) {
                const int r = (wm * 32 + mt * 16 + gid) * ALD + ks * 8 + tg;
                a[mt][0] = __float_as_uint(As[r]);
                a[mt][1] = __float_as_uint(As[r + 8 * ALD]);
                a[mt][2] = __float_as_uint(As[r + 4]);
                a[mt][3] = __float_as_uint(As[r + 8 * ALD + 4]);
            }
#pragma unroll
            for (int nt = 0; nt < 8; ++nt) {
                const int nidx = wn * 64 + nt * 8 + gid;
                const unsigned b0 = __float_as_uint(Bs[(ks * 8 + tg) * BLD + nidx]);
                const unsigned b1 = __float_as_uint(Bs[(ks * 8 + tg + 4) * BLD + nidx]);
                mma_tf32(c[0][nt], a[0], b0, b1);
                mma_tf32(c[1][nt], a[1], b0, b1);
            }
        }
    }

#pragma unroll
    for (int mt = 0; mt < 2; ++mt) {
#pragma unroll
        for (int nt = 0; nt < 8; ++nt) {
#pragma unroll
            for (int e = 0; e < 4; ++e) {
                const int m   = rowBase + wm * 32 + mt * 16 + gid + (e >> 1) * 8;
                const int col = colBase + wn * 64 + nt * 8 + tg * 2 + (e & 1);
                const float v = c[mt][nt][e];
                if (MODE == 0) {
                    C[(size_t)m * ldc + col] = v + bias[col];
                } else if (MODE == 1) {
                    float s = 1.f / (1.f + expf(-(gdp[(size_t)m * G3 + col] + v)));
                    if (col < D_) {
                        udp[(size_t)m * D_ + col] = s;
                    } else {
                        const int d = col - D_;
                        rxp[(size_t)m * D_ + d] =
                            __uint_as_float(f2tf(s * xp[(size_t)m * D_ + d]));
                    }
                } else {
                    float hcd = tanhf(gdp[(size_t)m * G3 + 2 * D_ + col] + v);
                    float xv  = xp[(size_t)m * D_ + col];
                    C[(size_t)m * D_ + col] =
                        fmaf(udp[(size_t)m * D_ + col], hcd - xv, xv);
                }
            }
        }
    }
}

// final_ht = ht[:, T-1, :]
__global__ void __launch_bounds__(256)
copy_final(float* __restrict__ out)
{
    int i = blockIdx.x * 256 + threadIdx.x;
    int n = i >> 10, h = i & 1023;
    out[i] = g_ht[(size_t)n * TT * H_ + (size_t)(TT - 1) * H_ + h];
}

// ----------------------------------------------------------------------------
extern "C" void kernel_launch(void* const* d_in, const int* in_sizes, int n_in,
                              void* d_out, int out_size)
{
    const float* x      = (const float*)d_in[0];
    const float* state  = (const float*)d_in[1];
    const float* weight = (const float*)d_in[2];
    const float* bias   = (const float*)d_in[3];
    float*       out    = (float*)d_out;

    float *gates, *ht32, *ud, *rx, *w32, *x32;
    cudaGetSymbolAddress((void**)&gates, g_gates);
    cudaGetSymbolAddress((void**)&ht32,  g_ht32);
    cudaGetSymbolAddress((void**)&ud,    g_ud);
    cudaGetSymbolAddress((void**)&rx,    g_rx);
    cudaGetSymbolAddress((void**)&w32,   g_w32);
    cudaGetSymbolAddress((void**)&x32,   g_x32);

    const dim3 blk(256);
    const int scan_smem = SMEM_FLOATS * 4;   // 161792 B

    cudaFuncSetAttribute(scan_kernel,
                         cudaFuncAttributeMaxDynamicSharedMemorySize, scan_smem);
    cudaFuncSetAttribute(tgemm2<0>,
                         cudaFuncAttributeMaxDynamicSharedMemorySize, GEMM_SMEM);
    cudaFuncSetAttribute(tgemm2<1>,
                         cudaFuncAttributeMaxDynamicSharedMemorySize, GEMM_SMEM);
    cudaFuncSetAttribute(tgemm2<2>,
                         cudaFuncAttributeMaxDynamicSharedMemorySize, GEMM_SMEM);

    // pre-convert weight / x / state to tf32 bits
    conv_kernel<<<1024, blk>>>(weight, x, state);

    // K1: gates = x @ Wxt + bias[:3H]
    tgemm2<0><<<dim3(G3 / 128, MROWS / 128), blk, GEMM_SMEM>>>(
        x32, 1024, w32, WLD, bias, gates, G3,
        nullptr, nullptr, nullptr, nullptr);

    // Persistent scan: 512 steps in ONE launch
    scan_kernel<<<NBLK_SCAN, blk, scan_smem>>>(weight, state);

    // K3: gd = ht @ Whd + bias[3H:]
    tgemm2<0><<<dim3(G3 / 128, MROWS / 128), blk, GEMM_SMEM>>>(
        ht32, 1024, w32 + (size_t)D_ * WLD + G3, WLD, bias + G3, gates, G3,
        nullptr, nullptr, nullptr, nullptr);

    // K4: g2 = sigmoid(gd[:, :2D] + x @ Wxd[:, :2D]) -> ud, rx
    tgemm2<1><<<dim3(2048 / 128, MROWS / 128), blk, GEMM_SMEM>>>(
        x32, 1024, w32 + G3, WLD, nullptr, nullptr, 0,
        gates, x, ud, rx);

    // K5: h = x + ud * (tanh(gd[:, 2D:] + rx @ Wxd[:, 2D:]) - x)
    tgemm2<2><<<dim3(1024 / 128, MROWS / 128), blk, GEMM_SMEM>>>(
        rx, 1024, w32 + G3 + 2 * D_, WLD, nullptr, out, D_,
        gates, x, ud, nullptr);

    // final_ht
    copy_final<<<128, blk>>>(out + (size_t)MROWS * D_);
}